// round 1
// baseline (speedup 1.0000x reference)
#include <cuda_runtime.h>

// Problem constants (fixed shapes)
#define NR      40962
#define NH      163842            // 4*NR - 6
#define NR7     286734            // NR*7
#define NBATCH  2
#define MROWS1  81924             // B*NR
#define MROWS2  327684            // B*NH
#define CIN     128
#define CO      64
#define N_UP    448               // 7*CO
#define K_UP    128
#define K_C1    896               // 7*CIN
#define K_C2    448               // 7*CO

// Scratch (device globals; allocation-free per harness rules)
__device__ float  g_h [MROWS1 * N_UP];    // up-GEMM output, viewed as [B, NR*7, 64]
__device__ float  g_x [MROWS2 * CIN];     // concat(x1_up, x2): [B, NH, 128]
__device__ float  g_t1[MROWS2 * CO];      // conv1 raw output
__device__ float  g_t2[MROWS2 * CO];      // conv2 raw output
__device__ double g_stats1[128];          // sum, sumsq per channel
__device__ double g_stats2[128];
__device__ float  g_sc1[64], g_bb1[64], g_sc2[64], g_bb2[64];

#define BM 64
#define BN 64
#define BK 16

// Tiled fp32 GEMM with optional A-row gather through neigh_orders.
// MODE 0: A direct [Mtot x K]              (up GEMM, out = A@W + bias)
// MODE 1: A[row, seg*128+c] = src[(b*NH + neigh[n*7+seg])*128 + c]
// MODE 2: A[row, seg*64+c]  = lrelu(src[(b*NH+neigh[n*7+seg])*64+c]*sc[c]+bb[c])
template<int MODE, int K>
__global__ __launch_bounds__(256)
void gemm_k(const float* __restrict__ A, const float* __restrict__ W,
            const float* __restrict__ bias, float* __restrict__ out,
            int Mtot, int Ntot,
            const int* __restrict__ neigh,
            const float* __restrict__ sc, const float* __restrict__ bb)
{
    __shared__ __align__(16) float As[BK][BM + 4];
    __shared__ __align__(16) float Bs[BK][BN];

    const int tid = threadIdx.x;
    const int tx  = tid & 15;
    const int ty  = tid >> 4;
    const int rowBase = blockIdx.y * BM;
    const int colBase = blockIdx.x * BN;

    // Rows this thread loads into As: ty + 16*i
    int nBase[4];   // n*7 for neigh lookup
    int bBase[4];   // b*NH
    bool rowOk[4];
#pragma unroll
    for (int i = 0; i < 4; i++) {
        int gr = rowBase + ty + 16 * i;
        rowOk[i] = (gr < Mtot);
        if (MODE != 0) {
            if (rowOk[i]) {
                int b = gr / NH;
                bBase[i] = b * NH;
                nBase[i] = (gr - b * NH) * 7;
            } else { bBase[i] = 0; nBase[i] = 0; }
        }
    }

    int srcRow[4] = {0, 0, 0, 0};
    float acc[4][4] = {};
    const int SEG = (MODE == 1) ? 128 : 64;

    for (int k0 = 0; k0 < K; k0 += BK) {
        if (MODE != 0 && (k0 % SEG) == 0) {
            int seg = k0 / SEG;
#pragma unroll
            for (int i = 0; i < 4; i++)
                if (rowOk[i]) srcRow[i] = bBase[i] + neigh[nBase[i] + seg];
        }
        // Load A tile (each thread: column tx of 4 fixed rows)
#pragma unroll
        for (int i = 0; i < 4; i++) {
            int r = ty + 16 * i;
            float v = 0.f;
            if (rowOk[i]) {
                if (MODE == 0) {
                    v = A[(rowBase + r) * K + k0 + tx];
                } else if (MODE == 1) {
                    v = A[srcRow[i] * 128 + ((k0 + tx) & 127)];
                } else {
                    int c = (k0 + tx) & 63;
                    float raw = A[srcRow[i] * 64 + c];
                    float t = raw * sc[c] + bb[c];
                    v = (t >= 0.f) ? t : 0.2f * t;
                }
            }
            As[tx][r] = v;
        }
        // Load B tile
#pragma unroll
        for (int i = 0; i < 4; i++) {
            int kk  = (tid >> 6) + 4 * i;
            int col = tid & 63;
            Bs[kk][col] = W[(k0 + kk) * Ntot + colBase + col];
        }
        __syncthreads();
#pragma unroll
        for (int kk = 0; kk < BK; kk++) {
            float4 a4 = *reinterpret_cast<const float4*>(&As[kk][ty * 4]);
            float4 b4 = *reinterpret_cast<const float4*>(&Bs[kk][tx * 4]);
            float av[4] = {a4.x, a4.y, a4.z, a4.w};
            float bv[4] = {b4.x, b4.y, b4.z, b4.w};
#pragma unroll
            for (int i = 0; i < 4; i++)
#pragma unroll
                for (int j = 0; j < 4; j++)
                    acc[i][j] += av[i] * bv[j];
        }
        __syncthreads();
    }

#pragma unroll
    for (int i = 0; i < 4; i++) {
        int gr = rowBase + ty * 4 + i;
        if (gr >= Mtot) continue;
#pragma unroll
        for (int j = 0; j < 4; j++) {
            int col = colBase + tx * 4 + j;
            out[(size_t)gr * Ntot + col] = acc[i][j] + bias[col];
        }
    }
}

// Build x = concat([upsample(h), x2], channels) -> [B, NH, 128]
__global__ void build_x_k(const float* __restrict__ h, const float* __restrict__ x2,
                          const int* __restrict__ topIdx, const int* __restrict__ downIdx,
                          float* __restrict__ x)
{
    int gr = blockIdx.x;                 // 0 .. MROWS2-1
    int c  = threadIdx.x;                // 0 .. 127
    int b  = gr / NH;
    int n  = gr - b * NH;
    float v;
    if (c < 64) {
        if (n < NR) {
            int j = topIdx[n];
            v = h[(b * NR7 + j) * 64 + c];
        } else {
            int m = n - NR;
            int i0 = downIdx[2 * m];
            int i1 = downIdx[2 * m + 1];
            v = 0.5f * (h[(b * NR7 + i0) * 64 + c] + h[(b * NR7 + i1) * 64 + c]);
        }
    } else {
        v = x2[(size_t)gr * 64 + (c - 64)];
    }
    x[(size_t)gr * 128 + c] = v;
}

__global__ void zero_stats_k()
{
    int i = threadIdx.x;
    if (i < 128) { g_stats1[i] = 0.0; g_stats2[i] = 0.0; }
}

__global__ void stats_k(const float* __restrict__ t, double* __restrict__ st)
{
    int c   = threadIdx.x & 63;
    int sub = threadIdx.x >> 6;          // 0..3
    double s = 0.0, sq = 0.0;
    for (int r = blockIdx.x * 4 + sub; r < MROWS2; r += gridDim.x * 4) {
        float v = t[(size_t)r * 64 + c];
        s  += v;
        sq += (double)v * (double)v;
    }
    __shared__ double sh[512];
    sh[threadIdx.x]       = s;
    sh[256 + threadIdx.x] = sq;
    __syncthreads();
    if (sub == 0) {
#pragma unroll
        for (int i = 1; i < 4; i++) { s += sh[c + 64 * i]; sq += sh[256 + c + 64 * i]; }
        atomicAdd(&st[c], s);
        atomicAdd(&st[64 + c], sq);
    }
}

__global__ void finalize_k(const double* __restrict__ st,
                           const float* __restrict__ gamma, const float* __restrict__ beta,
                           float* __restrict__ sc, float* __restrict__ bb)
{
    int c = threadIdx.x;
    if (c < 64) {
        double inv   = 1.0 / (double)MROWS2;
        double mean  = st[c] * inv;
        double var   = st[64 + c] * inv - mean * mean;
        double scale = (double)gamma[c] / sqrt(var + 1e-5);
        sc[c] = (float)scale;
        bb[c] = (float)((double)beta[c] - mean * scale);
    }
}

__global__ void apply_k(const float* __restrict__ t, const float* __restrict__ sc,
                        const float* __restrict__ bb, float* __restrict__ out)
{
    int i      = blockIdx.x * blockDim.x + threadIdx.x;
    int stride = gridDim.x * blockDim.x;
    const int total = MROWS2 * CO;
    for (; i < total; i += stride) {
        int c = i & 63;
        float v = t[i] * sc[c] + bb[c];
        out[i] = (v >= 0.f) ? v : 0.2f * v;
    }
}

extern "C" void kernel_launch(void* const* d_in, const int* in_sizes, int n_in,
                              void* d_out, int out_size)
{
    const float* x1    = (const float*)d_in[0];
    const float* x2    = (const float*)d_in[1];
    const int*   neigh = (const int*)  d_in[2];
    const int*   topI  = (const int*)  d_in[3];
    const int*   downI = (const int*)  d_in[4];
    const float* upW   = (const float*)d_in[5];
    const float* upB   = (const float*)d_in[6];
    const float* c1W   = (const float*)d_in[7];
    const float* c1b   = (const float*)d_in[8];
    const float* gam1  = (const float*)d_in[9];
    const float* bet1  = (const float*)d_in[10];
    const float* c2W   = (const float*)d_in[11];
    const float* c2b   = (const float*)d_in[12];
    const float* gam2  = (const float*)d_in[13];
    const float* bet2  = (const float*)d_in[14];
    float* out = (float*)d_out;

    float *h, *x, *t1, *t2, *sc1, *bb1, *sc2, *bb2;
    double *st1, *st2;
    cudaGetSymbolAddress((void**)&h,   g_h);
    cudaGetSymbolAddress((void**)&x,   g_x);
    cudaGetSymbolAddress((void**)&t1,  g_t1);
    cudaGetSymbolAddress((void**)&t2,  g_t2);
    cudaGetSymbolAddress((void**)&st1, g_stats1);
    cudaGetSymbolAddress((void**)&st2, g_stats2);
    cudaGetSymbolAddress((void**)&sc1, g_sc1);
    cudaGetSymbolAddress((void**)&bb1, g_bb1);
    cudaGetSymbolAddress((void**)&sc2, g_sc2);
    cudaGetSymbolAddress((void**)&bb2, g_bb2);

    zero_stats_k<<<1, 128>>>();

    // 1) up GEMM: [81924 x 128] @ [128 x 448] + up_b -> h
    {
        dim3 grid(N_UP / BN, (MROWS1 + BM - 1) / BM);
        gemm_k<0, K_UP><<<grid, 256>>>(x1, upW, upB, h, MROWS1, N_UP,
                                       nullptr, nullptr, nullptr);
    }

    // 2) build x = concat(upsample(h), x2)
    build_x_k<<<MROWS2, 128>>>(h, x2, topI, downI, x);

    // 3) conv1: gather(x, neigh) [327684 x 896] @ [896 x 64] + b -> t1
    {
        dim3 grid(1, (MROWS2 + BM - 1) / BM);
        gemm_k<1, K_C1><<<grid, 256>>>(x, c1W, c1b, t1, MROWS2, CO,
                                       neigh, nullptr, nullptr);
    }

    // 4) BN1 stats + finalize
    stats_k<<<512, 256>>>(t1, st1);
    finalize_k<<<1, 64>>>(st1, gam1, bet1, sc1, bb1);

    // 5) conv2: gather(lrelu(bn1(t1)), neigh) [327684 x 448] @ [448 x 64] + b -> t2
    {
        dim3 grid(1, (MROWS2 + BM - 1) / BM);
        gemm_k<2, K_C2><<<grid, 256>>>(t1, c2W, c2b, t2, MROWS2, CO,
                                       neigh, sc1, bb1);
    }

    // 6) BN2 stats + finalize
    stats_k<<<512, 256>>>(t2, st2);
    finalize_k<<<1, 64>>>(st2, gam2, bet2, sc2, bb2);

    // 7) out = lrelu(bn2(t2))
    apply_k<<<2048, 256>>>(t2, sc2, bb2, out);
}